// round 9
// baseline (speedup 1.0000x reference)
#include <cuda_runtime.h>

// x (B,L,C,H,W) = (2,24,32,128,256) fp32, params (2,C,R) = (2,32,32) fp32.
// Exact causal FIR conv along L (reference rfft(48) has no aliasing, 2L-1=47<=48).
//
// R9: x reads via cp.async.bulk (TMA path) into smem, bypassing the per-SM
// L1tex wavefront queue that caps outstanding read lines (~250/SM) below the
// bandwidth-delay product -- the suspected reason DRAM sits at 77% regardless
// of occupancy. 23 l-streams arrive as 2KB bulk copies (mbarrier, expect_tx);
// the 24th stays a direct LDG to keep static smem < 48KB. MAC unchanged
// (packed fma.rn.f32x2), stores stay STG.cs.

#define B_ 2
#define L_ 24
#define C_ 32
#define H_ 128
#define W_ 256
#define R_ 32

#define L_TMA 23                       // l-streams delivered via bulk copy
#define TILE_PIX 256                   // float2 pixels per block
#define SLOT_B (TILE_PIX * 8)          // 2048 bytes per l-slot
#define TX_BYTES (L_TMA * SLOT_B)      // 47104

__global__ __launch_bounds__(256, 3)
void ConvLRU_tma_kernel(const unsigned long long* __restrict__ x,
                        const float*              __restrict__ p,
                        unsigned long long*       __restrict__ y) {
    constexpr int HW2     = H_ * (W_ / 2);   // 16384 = 2^14
    constexpr int strideL = C_ * HW2;        // 64-bit elems between consecutive l

    __shared__ __align__(16) unsigned long long sx[L_TMA * TILE_PIX]; // 47104 B
    __shared__ float sk[L_];
    __shared__ __align__(8) unsigned long long smbar;

    int tid = threadIdx.x;
    int gid = blockIdx.x * 256 + tid;                 // bits: [0:14)=hw [14:19)=c [19]=b
    int c   = (gid >> 14) & (C_ - 1);
    int base = gid + (gid >> 19) * ((L_ - 1) * strideL);   // 64-bit idx of (b,0,c,hw)

    unsigned int mbar_a, sx_a;
    asm("{ .reg .u64 t; cvta.to.shared.u64 t, %1; cvt.u32.u64 %0, t; }"
        : "=r"(mbar_a) : "l"(&smbar));
    asm("{ .reg .u64 t; cvta.to.shared.u64 t, %1; cvt.u32.u64 %0, t; }"
        : "=r"(sx_a) : "l"(sx));

    // ---- init mbarrier ----
    if (tid == 0) {
        asm volatile("mbarrier.init.shared.b64 [%0], 1;" :: "r"(mbar_a) : "memory");
    }
    __syncthreads();

    // ---- the one LDG stream (l = 23), issued early to overlap ----
    unsigned long long xv[L_];
    xv[L_ - 1] = __ldcs(&x[base + (L_ - 1) * strideL]);

    // ---- thread 0 issues expect_tx + 23 bulk copies (2KB each) ----
    if (tid == 0) {
        asm volatile("mbarrier.arrive.expect_tx.shared.b64 _, [%0], %1;"
                     :: "r"(mbar_a), "r"((unsigned)TX_BYTES) : "memory");
        const char* src0 = (const char*)(x + base);   // tid==0 -> block base
#pragma unroll
        for (int l = 0; l < L_TMA; l++) {
            const char* src = src0 + (size_t)l * strideL * 8;
            asm volatile(
                "cp.async.bulk.shared::cluster.global.mbarrier::complete_tx::bytes "
                "[%0], [%1], %2, [%3];"
                :: "r"(sx_a + l * SLOT_B), "l"(src), "r"((unsigned)SLOT_B), "r"(mbar_a)
                : "memory");
        }
    }

    // ---- k[c][t] = sum_r gamma*exp(-t*nu)*cos(t*theta); hides under TMA ----
    {
        int lane = tid & 31;
        int wrp  = tid >> 5;
        float nu_log    = p[c * R_ + lane];
        float theta_log = p[C_ * R_ + c * R_ + lane];
        float nu    = __expf(nu_log);
        float theta = __expf(theta_log);
        float lam2  = __expf(-2.0f * nu);
        float gamma = sqrtf(fmaxf(1.0f - lam2, 1e-12f));
#pragma unroll
        for (int j = 0; j < 3; j++) {
            int   t  = 8 * j + wrp;
            float tf = (float)t;
            float term = gamma * __expf(-tf * nu) * __cosf(tf * theta);
#pragma unroll
            for (int off = 16; off > 0; off >>= 1)
                term += __shfl_xor_sync(0xFFFFFFFFu, term, off);
            if (lane == 0) sk[t] = term;
        }
    }
    __syncthreads();   // sk visible to all warps

    // ---- wait for all 23 bulk copies (parity 0, acquire) ----
    {
        unsigned done;
        asm volatile(
            "{\n\t.reg .pred q;\n\t"
            "mbarrier.try_wait.parity.acquire.cta.shared::cta.b64 q, [%1], 0;\n\t"
            "selp.b32 %0, 1, 0, q;\n\t}"
            : "=r"(done) : "r"(mbar_a) : "memory");
        if (!done) {
            asm volatile(
                "{\n\t.reg .pred q;\n\t"
                "WAITLOOP:\n\t"
                "mbarrier.try_wait.parity.acquire.cta.shared::cta.b64 q, [%0], 0, 0x989680;\n\t"
                "@q bra.uni WAITDONE;\n\t"
                "bra.uni WAITLOOP;\n\t"
                "WAITDONE:\n\t}"
                :: "r"(mbar_a) : "memory");
        }
    }

    // ---- pull tile into registers (conflict-free LDS.64) ----
#pragma unroll
    for (int l = 0; l < L_TMA; l++) {
        xv[l] = sx[l * TILE_PIX + tid];
    }

    // ---- triangular causal MAC with packed f32x2 FMAs + streaming stores ----
#pragma unroll
    for (int l = 0; l < L_; l++) {
        unsigned long long acc = 0ull;
#pragma unroll
        for (int t = 0; t <= l; t++) {
            float kv = sk[t];
            unsigned long long kk;
            asm("mov.b64 %0, {%1, %1};" : "=l"(kk) : "r"(__float_as_uint(kv)));
            asm("fma.rn.f32x2 %0, %1, %2, %0;" : "+l"(acc) : "l"(xv[l - t]), "l"(kk));
        }
        __stcs(&y[base + l * strideL], acc);
    }
}

extern "C" void kernel_launch(void* const* d_in, const int* in_sizes, int n_in,
                              void* d_out, int out_size) {
    const float* x = (const float*)d_in[0];        // (B,L,C,H,W)
    const float* p = (const float*)d_in[1];        // (2,C,R)
    float* y = (float*)d_out;

    constexpr int total2 = B_ * C_ * H_ * (W_ / 2);  // 1048576
    ConvLRU_tma_kernel<<<total2 / 256, 256>>>(
        (const unsigned long long*)x, p, (unsigned long long*)y);
}

// round 10
// speedup vs baseline: 1.0164x; 1.0164x over previous
#include <cuda_runtime.h>

// x (B,L,C,H,W) = (2,24,32,128,256) fp32, params (2,C,R) = (2,32,32) fp32.
// Exact causal FIR conv along L (reference rfft(48) has no aliasing, 2L-1=47<=48).
//
// R10 = R8 (best config) with ONE change: y stores use default write-back
// policy instead of .cs. Evict-first stores force immediate per-line
// writebacks, finely interleaving writes into the read stream (max HBM
// turnarounds); default policy lets L2 batch writebacks into large
// same-direction bursts. x lines have zero reuse, so y displacing them is free.
// Dead ends so far: persistent grid (R3), occupancy (R5), L2 pinning (R6/7,
// carveout rule-blocked), TMA loads (R9).

#define B_ 2
#define L_ 24
#define C_ 32
#define H_ 128
#define W_ 256
#define R_ 32

__global__ __launch_bounds__(256, 3)
void ConvLRU_fused_kernel(const unsigned long long* __restrict__ x,
                          const float*              __restrict__ p,
                          unsigned long long*       __restrict__ y) {
    constexpr int HW2     = H_ * (W_ / 2);   // 16384 = 2^14
    constexpr int strideL = C_ * HW2;        // 524288 64-bit elems between l's

    // gid bit-layout: bits [0:14) = hw, [14:19) = c, [19] = b
    int gid = blockIdx.x * 256 + threadIdx.x;              // over 2^20
    int c   = (gid >> 14) & (C_ - 1);
    int base = gid + (gid >> 19) * ((L_ - 1) * strideL);   // 64-bit idx of l=0

    __shared__ float sk[L_];

    // ---- issue all 24 sequence loads first (deep MLP, nc + evict-first) ----
    unsigned long long xv[L_];
#pragma unroll
    for (int l = 0; l < L_; l++) {
        const unsigned long long* ptr = &x[base + l * strideL];
        asm("ld.global.nc.cs.b64 %0, [%1];" : "=l"(xv[l]) : "l"(ptr));
    }

    // ---- k[c][t] = sum_r gamma*exp(-t*nu)*cos(t*theta); hides under loads ----
    {
        int lane = threadIdx.x & 31;       // = rank r
        int wrp  = threadIdx.x >> 5;       // warp id 0..7
        float nu_log    = p[c * R_ + lane];
        float theta_log = p[C_ * R_ + c * R_ + lane];
        float nu    = __expf(nu_log);
        float theta = __expf(theta_log);
        float lam2  = __expf(-2.0f * nu);
        float gamma = sqrtf(fmaxf(1.0f - lam2, 1e-12f));
#pragma unroll
        for (int j = 0; j < 3; j++) {
            int   t  = 8 * j + wrp;        // each warp covers t = w, w+8, w+16
            float tf = (float)t;
            float term = gamma * __expf(-tf * nu) * __cosf(tf * theta);
#pragma unroll
            for (int off = 16; off > 0; off >>= 1)
                term += __shfl_xor_sync(0xFFFFFFFFu, term, off);
            if (lane == 0) sk[t] = term;
        }
    }

    __syncthreads();   // sk visible; xv loads still in flight

    // ---- triangular causal MAC (f32x2) + default write-back stores ----
#pragma unroll
    for (int l = 0; l < L_; l++) {
        unsigned long long acc = 0ull;     // {0.f, 0.f}
#pragma unroll
        for (int t = 0; t <= l; t++) {
            float kv = sk[t];
            unsigned long long kk;
            asm("mov.b64 %0, {%1, %1};" : "=l"(kk) : "r"(__float_as_uint(kv)));
            asm("fma.rn.f32x2 %0, %1, %2, %0;" : "+l"(acc) : "l"(xv[l - t]), "l"(kk));
        }
        y[base + l * strideL] = acc;       // default policy: L2 batches writebacks
    }
}

extern "C" void kernel_launch(void* const* d_in, const int* in_sizes, int n_in,
                              void* d_out, int out_size) {
    const float* x = (const float*)d_in[0];        // (B,L,C,H,W)
    const float* p = (const float*)d_in[1];        // (2,C,R)
    float* y = (float*)d_out;

    constexpr int total2 = B_ * C_ * H_ * (W_ / 2);  // 1048576
    ConvLRU_fused_kernel<<<total2 / 256, 256>>>(
        (const unsigned long long*)x, p, (unsigned long long*)y);
}